// round 7
// baseline (speedup 1.0000x reference)
#include <cuda_runtime.h>
#include <math.h>
#include <stdint.h>

#define BB 16
#define AA 65472
#define CC 81
#define GG 50
#define NBIN 32768
#define NSTRIP 16

__device__ float  g_best_iou[BB * AA];
__device__ int    g_best_idx[BB * AA];
__device__ int    g_labels[BB * AA];
__device__ float  g_mining[BB * AA];
__device__ unsigned long long g_gt_pack[BB * GG];
__device__ int    g_num_pos[BB];
__device__ double g_topk_sum[BB];
__device__ double g_loc_sum;
__device__ double g_ce_sum;

__device__ __forceinline__ float sl1_loss(float4 an, const float* __restrict__ gp, float4 p) {
    float acx = (an.x + an.z) * 0.5f, acy = (an.y + an.w) * 0.5f;
    float aw = an.z - an.x, ah = an.w - an.y;
    float mcx = (gp[0] + gp[2]) * 0.5f, mcy = (gp[1] + gp[3]) * 0.5f;
    float mw = gp[2] - gp[0], mh = gp[3] - gp[1];
    float t0 = (mcx - acx) / (aw * 0.1f);
    float t1 = (mcy - acy) / (ah * 0.1f);
    float t2 = logf(mw / aw + 1e-10f) * 5.0f;
    float t3 = logf(mh / ah + 1e-10f) * 5.0f;
    float n0 = fabsf(p.x - t0), n1 = fabsf(p.y - t1);
    float n2 = fabsf(p.z - t2), n3 = fabsf(p.w - t3);
    const float BETA = 1.0f / 9.0f;
    return (n0 < BETA ? 4.5f * n0 * n0 : n0 - 0.5f * BETA)
         + (n1 < BETA ? 4.5f * n1 * n1 : n1 - 0.5f * BETA)
         + (n2 < BETA ? 4.5f * n2 * n2 : n2 - 0.5f * BETA)
         + (n3 < BETA ? 4.5f * n3 * n3 : n3 - 0.5f * BETA);
}

__global__ void k_init() {
    int i = threadIdx.x;
    if (i < BB * GG) g_gt_pack[i] = 0xFFFFFFFFull;
    if (i < BB) { g_num_pos[i] = 0; g_topk_sum[i] = 0.0; }
    if (i == 0) { g_loc_sum = 0.0; g_ce_sum = 0.0; }
}

__device__ __forceinline__ int stripc(float x) {
    int s = (int)(x * (float)NSTRIP);
    return s < 0 ? 0 : (s > NSTRIP - 1 ? NSTRIP - 1 : s);
}

// match + labels + localisation loss + num_pos, with strip-mask pruning
__global__ void __launch_bounds__(256) k_match(const float* __restrict__ gts,
                                               const int* __restrict__ counts,
                                               const float* __restrict__ anchors,
                                               const float* __restrict__ pred) {
    int b = blockIdx.y;
    int a = blockIdx.x * 256 + threadIdx.x;
    __shared__ float4 sbox[GG];
    __shared__ float  sarea[GG];
    __shared__ float  slab[GG];
    __shared__ unsigned long long spack[GG];
    __shared__ unsigned long long mx[NSTRIP], my[NSTRIP];
    __shared__ double s_loc;
    __shared__ int s_np;
    int t = threadIdx.x;
    int count = counts[b];
    if (t < NSTRIP) { mx[t] = 0ull; my[t] = 0ull; }
    if (t == 0) { s_loc = 0.0; s_np = 0; }
    if (t < GG) {
        const float* gp = gts + ((size_t)b * GG + t) * 5;
        float4 bx = make_float4(gp[0], gp[1], gp[2], gp[3]);
        sbox[t] = bx;
        sarea[t] = (bx.z - bx.x) * (bx.w - bx.y) + 1e-10f;
        slab[t] = gp[4];
        spack[t] = 0ull;
    }
    __syncthreads();
    if (t < count) {
        float4 bx = sbox[t];
        unsigned long long bit = 1ull << t;
        for (int s = stripc(bx.x); s <= stripc(bx.z); s++) atomicOr(&mx[s], bit);
        for (int s = stripc(bx.y); s <= stripc(bx.w); s++) atomicOr(&my[s], bit);
    }
    __syncthreads();
    float lsum = 0.0f;
    int ispos = 0;
    if (a < AA) {
        float4 an = ((const float4*)anchors)[a];
        float areaA = (an.z - an.x) * (an.w - an.y);
        unsigned long long m = 0ull, m2 = 0ull;
        for (int s = stripc(an.x); s <= stripc(an.z); s++) m |= mx[s];
        for (int s = stripc(an.y); s <= stripc(an.w); s++) m2 |= my[s];
        m &= m2;
        float best_q = 0.0f;
        int best_g = 0;
        unsigned int inva = 0xFFFFFFFFu - (unsigned int)a;
        while (m) {
            int g = __ffsll(m) - 1;
            m &= m - 1;
            float4 bx = sbox[g];
            float wx = fminf(an.z, bx.z) - fmaxf(an.x, bx.x);
            float wy = fminf(an.w, bx.w) - fmaxf(an.y, bx.y);
            wx = fmaxf(wx, 0.0f); wy = fmaxf(wy, 0.0f);
            float inter = wx * wy;
            float q = __fdividef(inter, areaA + sarea[g] - inter);
            if (q > best_q) { best_q = q; best_g = g; }       // first-max (asc g)
            if (inter > 0.0f) {
                unsigned long long pk =
                    (((unsigned long long)__float_as_uint(q)) << 32) | inva;
                if (pk > spack[g]) atomicMax(&spack[g], pk);  // racy read = filter
            }
        }
        size_t idx = (size_t)b * AA + a;
        g_best_iou[idx] = best_q;
        g_best_idx[idx] = best_g;
        int label = 0;
        if (best_q >= 0.5f) {
            label = (int)slab[best_g];
            ispos = 1;
            const float* gp = gts + ((size_t)b * GG + best_g) * 5;
            lsum = sl1_loss(an, gp, ((const float4*)pred)[idx]);
        }
        g_labels[idx] = label;
    }
    for (int o = 16; o; o >>= 1) {
        lsum  += __shfl_down_sync(0xffffffffu, lsum, o);
        ispos += __shfl_down_sync(0xffffffffu, ispos, o);
    }
    if ((threadIdx.x & 31) == 0 && ispos) {
        atomicAdd(&s_np, ispos);
        atomicAdd(&s_loc, (double)lsum);
    }
    __syncthreads();
    if (t == 0 && s_np) {
        atomicAdd(&g_num_pos[b], s_np);
        atomicAdd(&g_loc_sum, s_loc);
    }
    if (t < count && spack[t]) atomicMax(&g_gt_pack[b * GG + t], spack[t]);
}

__global__ void k_force(const float* __restrict__ gts,
                        const int* __restrict__ counts,
                        const float* __restrict__ anchors,
                        const float* __restrict__ pred) {
    int b = blockIdx.x;
    int j = threadIdx.x;
    __shared__ unsigned int sa[GG];
    int count = counts[b];
    unsigned int a = 0;
    if (j < count) {
        unsigned long long pk = g_gt_pack[b * GG + j];
        a = 0xFFFFFFFFu - (unsigned int)(pk & 0xFFFFFFFFull);
        sa[j] = a;
    }
    __syncthreads();
    if (j < count) {
        bool ok = true;                          // duplicate scatter: last j wins
        for (int j2 = j + 1; j2 < count; j2++)
            if (sa[j2] == a) ok = false;
        if (ok) {
            size_t idx = (size_t)b * AA + a;
            float q_old = g_best_iou[idx];
            int g_old = g_best_idx[idx];
            float4 an = ((const float4*)anchors)[a];
            float4 p = ((const float4*)pred)[idx];
            float loc_old = 0.0f;
            if (q_old >= 0.5f)
                loc_old = sl1_loss(an, gts + ((size_t)b * GG + g_old) * 5, p);
            else
                atomicAdd(&g_num_pos[b], 1);
            const float* gp = gts + ((size_t)b * GG + j) * 5;
            float loc_new = sl1_loss(an, gp, p);
            atomicAdd(&g_loc_sum, (double)loc_new - (double)loc_old);
            g_labels[idx] = (int)gp[4];
        }
    }
}

// thread-per-row, 128 rows per block (41.5KB smem -> 5 blocks/SM)
__global__ void __launch_bounds__(128) k_conf(const float* __restrict__ conf) {
    extern __shared__ float s[];                     // 128*81 floats = 41472 B
    __shared__ double sce[4];
    size_t rowbase = (size_t)blockIdx.x * 128;       // 8184 blocks exact
    const float4* src = (const float4*)(conf + rowbase * CC);
#pragma unroll 4
    for (int i = threadIdx.x; i < 128 * CC / 4; i += 128)
        ((float4*)s)[i] = src[i];
    int label = g_labels[rowbase + threadIdx.x];
    __syncthreads();
    const float* row = s + threadIdx.x * CC;         // stride 81: conflict-free
    float e0 = 0.f, e1 = 0.f, e2 = 0.f, e3 = 0.f;
#pragma unroll
    for (int i = 0; i < 80; i += 4) {
        e0 += __expf(row[i]);
        e1 += __expf(row[i + 1]);
        e2 += __expf(row[i + 2]);
        e3 += __expf(row[i + 3]);
    }
    e0 += __expf(row[80]);
    float lse = __logf((e0 + e1) + (e2 + e3));
    float ce = 0.0f;
    float m;
    if (label > 0) {
        ce = lse - row[label];
        m = __int_as_float(0xff800000);              // -inf marker (bit31 set)
    } else {
        m = lse - row[0];                            // > 0 always
    }
    g_mining[rowbase + threadIdx.x] = m;
    for (int o = 16; o; o >>= 1) ce += __shfl_down_sync(0xffffffffu, ce, o);
    if ((threadIdx.x & 31) == 0) sce[threadIdx.x >> 5] = (double)ce;
    __syncthreads();
    if (threadIdx.x == 0) {
        double tot = sce[0] + sce[1] + sce[2] + sce[3];
        if (tot != 0.0) atomicAdd(&g_ce_sum, tot);
    }
}

// fused top-k: one block per batch, smem hist + 3 L2-resident scans
__global__ void __launch_bounds__(1024) k_topk() {
    extern __shared__ unsigned int sh[];             // NBIN uints = 128 KB
    __shared__ unsigned int scnt[256];
    __shared__ unsigned int hc[256];
    __shared__ double hsum[256];
    __shared__ double sred[32];
    __shared__ unsigned int s_thr;
    __shared__ int s_r, s_b1, s_r1;
    __shared__ double s_sum2;
    int b = blockIdx.x;
    int t = threadIdx.x;
    const float* mine = g_mining + (size_t)b * AA;

    for (int i = t; i < NBIN; i += 1024) sh[i] = 0;
    __syncthreads();
    // scan 1: histogram
#pragma unroll 4
    for (int i = t; i < AA; i += 1024) {
        unsigned int u = __float_as_uint(mine[i]);
        if ((int)u >= 0) atomicAdd(&sh[u >> 16], 1u);
    }
    __syncthreads();
    // threshold walk
    int np = g_num_pos[b];
    long long kk = 3LL * np;
    int neg = AA - np;
    int k = (kk < (long long)neg) ? (int)kk : neg;
    if (t < 256) {
        int lo = NBIN - (t + 1) * 128;
        unsigned int c = 0;
        for (int i = 0; i < 128; i++) c += sh[lo + i];
        scnt[t] = c;
    }
    __syncthreads();
    if (t == 0) {
        if (k <= 0) { s_thr = 0xFFFFFFFFu; s_r = 0; }
        else {
            int cum = 0; int j = 0;
            for (; j < 256; j++) {
                if (cum + (int)scnt[j] >= k) break;
                cum += (int)scnt[j];
            }
            int hi = NBIN - j * 128 - 1;
            int bin = hi; int r = k - cum;
            for (int i = 0; i < 128; i++) {
                bin = hi - i;
                int cc = (int)sh[bin];
                if (cum + cc >= k) { r = k - cum; break; }
                cum += cc;
            }
            s_thr = (unsigned int)bin; s_r = r;
        }
    }
    __syncthreads();
    unsigned int thr = s_thr;
    int r = s_r;
    if (r == 0) { if (t == 0) g_topk_sum[b] = 0.0; return; }
    // scan 2: sum strictly above thr bin + 256-bin sub-hist of thr-bin elems
    if (t < 256) { hc[t] = 0; hsum[t] = 0.0; }
    __syncthreads();
    double acc = 0.0;
#pragma unroll 2
    for (int i = t; i < AA; i += 1024) {
        float v = mine[i];
        unsigned int u = __float_as_uint(v);
        if ((int)u >= 0) {
            unsigned int bin = u >> 16;
            if (bin > thr) acc += (double)v;
            else if (bin == thr) {
                atomicAdd(&hc[(u >> 8) & 255u], 1u);
                atomicAdd(&hsum[(u >> 8) & 255u], (double)v);
            }
        }
    }
    for (int o = 16; o; o >>= 1) acc += __shfl_down_sync(0xffffffffu, acc, o);
    if ((t & 31) == 0) sred[t >> 5] = acc;
    __syncthreads();
    if (t == 0) {
        double sumabove = 0.0;
        for (int i = 0; i < 32; i++) sumabove += sred[i];
        sred[0] = sumabove;
        int cum = 0; double s2 = 0.0; int bin = 255;
        for (bin = 255; bin >= 0; bin--) {
            int cc = (int)hc[bin];
            if (cum + cc >= r) break;
            cum += cc; s2 += hsum[bin];
        }
        s_b1 = bin; s_r1 = r - cum; s_sum2 = s2;
    }
    __syncthreads();
    int b1 = s_b1, r1 = s_r1;
    if (t < 256) { hc[t] = 0; hsum[t] = 0.0; }
    __syncthreads();
    // scan 3: final byte refinement among (thr, b1) elements
#pragma unroll 2
    for (int i = t; i < AA; i += 1024) {
        float v = mine[i];
        unsigned int u = __float_as_uint(v);
        if ((int)u >= 0 && (u >> 8) == ((thr << 8) | (unsigned)b1)) {
            atomicAdd(&hc[u & 255u], 1u);
            atomicAdd(&hsum[u & 255u], (double)v);
        }
    }
    __syncthreads();
    if (t == 0) {
        int cum = 0; double s3 = 0.0; int bin = 255;
        for (bin = 255; bin >= 0; bin--) {
            int cc = (int)hc[bin];
            if (cum + cc >= r1) break;
            cum += cc; s3 += hsum[bin];
        }
        int r2 = r1 - cum;                            // exact 32-bit ties
        unsigned int fb = (thr << 16) | ((unsigned)b1 << 8) | (unsigned)bin;
        g_topk_sum[b] = sred[0] + s_sum2 + s3 + (double)r2 * (double)__uint_as_float(fb);
    }
}

__global__ void k_final(float* __restrict__ out) {
    long long np = 0;
    double tk = 0.0;
    for (int b = 0; b < BB; b++) { np += g_num_pos[b]; tk += g_topk_sum[b]; }
    double num_pos = (np < 1) ? 1.0 : (double)np;
    double inv = 1.0 / (num_pos * 4.0);
    out[0] = (float)(g_loc_sum * inv);
    out[1] = (float)((g_ce_sum + tk) * inv);
}

extern "C" void kernel_launch(void* const* d_in, const int* in_sizes, int n_in,
                              void* d_out, int out_size) {
    const float* conf    = (const float*)d_in[0];
    const float* pred    = (const float*)d_in[1];
    const float* gts     = (const float*)d_in[2];
    const int*   counts  = (const int*)  d_in[3];
    const float* anchors = (const float*)d_in[4];
    float* out = (float*)d_out;

    static int attr_set = 0;
    if (!attr_set) {
        cudaFuncSetAttribute(k_topk, cudaFuncAttributeMaxDynamicSharedMemorySize,
                             NBIN * sizeof(unsigned int));
        attr_set = 1;
    }

    k_init<<<1, 1024>>>();
    dim3 gm((AA + 255) / 256, BB);
    k_match<<<gm, 256>>>(gts, counts, anchors, pred);
    k_force<<<BB, GG>>>(gts, counts, anchors, pred);
    k_conf<<<(BB * AA) / 128, 128, 128 * CC * sizeof(float)>>>(conf);
    k_topk<<<BB, 1024, NBIN * sizeof(unsigned int)>>>();
    k_final<<<1, 1>>>(out);
}